// round 16
// baseline (speedup 1.0000x reference)
#include <cuda_runtime.h>
#include <cuda_fp16.h>
#include <cstdint>

#define BATCH   524288
#define DIM     64
#define NE      8
#define NH      64
#define GHID    32

#define TILE_M  128
#define NTILES  (BATCH / TILE_M)   // 4096
#define GRID    296                // 2 CTAs per SM
#define THREADS 256
#define NSUB    8

// ---------------- smem byte layout ----------------
#define OFF_RAW    0        // raw fp32 x [128][64] staged via cp.async = 32768
#define OFF_XHI    32768    // fp16 [128][64] SW128 = 16384
#define OFF_ST     49152    // fp32 S transposed [32][129] = 16512
#define OFF_GW1    65664    // fp32 [32][32] = 4096
#define OFF_GW2    69760    // fp32 [32][8] = 1024
#define OFF_GB1    70784    // fp32 [32] = 128
#define OFF_GB2    70912    // fp32 [8] = 32
#define OFF_PROB   70944    // fp32 [128][9] = 4608 (pitch 9, conflict-free)
#define OFF_EO     75552    // fp32 [128][9] = 4608
#define OFF_W2S    80160    // fp32 [8][64] = 2048
#define OFF_B1S    82208    // fp32 [8][64] = 2048
#define SMEM_BYTES 84256

#define SW(o) ((o) ^ (((o) >> 3) & 0x70))

static __device__ __forceinline__ uint32_t smem_u32(const void* p) {
    uint32_t a;
    asm("{ .reg .u64 t; cvta.to.shared.u64 t, %1; cvt.u32.u64 %0, t; }" : "=r"(a) : "l"(p));
    return a;
}
static __device__ __forceinline__ void cpasync16(uint32_t dst, const void* src) {
    size_t g = __cvta_generic_to_global(src);
    asm volatile("cp.async.cg.shared.global [%0], [%1], 16;" :: "r"(dst), "l"(g) : "memory");
}
#define CP_COMMIT asm volatile("cp.async.commit_group;" ::: "memory")
#define CP_WAIT0  asm volatile("cp.async.wait_group 0;" ::: "memory")

static __device__ __forceinline__ void ldsm4(uint32_t* r, uint32_t addr) {
    asm volatile("ldmatrix.sync.aligned.m8n8.x4.shared.b16 {%0,%1,%2,%3}, [%4];"
                 : "=r"(r[0]), "=r"(r[1]), "=r"(r[2]), "=r"(r[3]) : "r"(addr));
}
static __device__ __forceinline__ void mma16816(float* c, const uint32_t* a,
                                                uint32_t b0, uint32_t b1) {
    asm volatile(
        "mma.sync.aligned.m16n8k16.row.col.f32.f16.f16.f32 "
        "{%0,%1,%2,%3}, {%4,%5,%6,%7}, {%8,%9}, {%0,%1,%2,%3};"
        : "+f"(c[0]), "+f"(c[1]), "+f"(c[2]), "+f"(c[3])
        : "r"(a[0]), "r"(a[1]), "r"(a[2]), "r"(a[3]), "r"(b0), "r"(b1));
}

typedef unsigned long long ull;
static __device__ __forceinline__ ull fma2(ull a, ull b, ull c) {
    ull d;
    asm("fma.rn.f32x2 %0, %1, %2, %3;" : "=l"(d) : "l"(a), "l"(b), "l"(c));
    return d;
}
static __device__ __forceinline__ ull pack2(float x, float y) {
    ull d;
    asm("mov.b64 %0, {%1, %2};" : "=l"(d) : "f"(x), "f"(y));
    return d;
}
static __device__ __forceinline__ void unpack2(ull v, float& x, float& y) {
    asm("mov.b64 {%0, %1}, %2;" : "=f"(x), "=f"(y) : "l"(v));
}
static __device__ __forceinline__ uint32_t packh2(float a, float b) {
    __half ha = __float2half_rn(a), hb = __float2half_rn(b);
    return ((uint32_t)__half_as_ushort(hb) << 16) | __half_as_ushort(ha);
}
static __device__ __forceinline__ uint32_t cvth2(float a, float b) {
    uint32_t r;
    asm("cvt.rn.f16x2.f32 %0, %1, %2;" : "=r"(r) : "f"(b), "f"(a));
    return r;
}

__global__ void __launch_bounds__(THREADS, 2)
moe_mma_kernel(const float* __restrict__ A,   const float* __restrict__ S,
               const float* __restrict__ gw1, const float* __restrict__ gb1,
               const float* __restrict__ gw2, const float* __restrict__ gb2,
               const float* __restrict__ ew1, const float* __restrict__ eb1,
               const float* __restrict__ ew2, const float* __restrict__ eb2,
               float* __restrict__ out)
{
    extern __shared__ char smem[];
    float* smf = (float*)smem;
    const uint32_t sbase = smem_u32(smem);
    const int tid  = threadIdx.x;
    const int lane = tid & 31;
    const int wid  = tid >> 5;          // warp == expert id

    // ---- stage small fp32 weights ----
    for (int i = tid; i < GHID * GHID; i += THREADS) smf[OFF_GW1 / 4 + i] = gw1[i];
    for (int i = tid; i < GHID * NE;   i += THREADS) smf[OFF_GW2 / 4 + i] = gw2[i];
    for (int i = tid; i < NE * NH;     i += THREADS) {
        smf[OFF_W2S / 4 + i] = ew2[i];
        smf[OFF_B1S / 4 + i] = eb1[i];
    }
    if (tid < GHID) smf[OFF_GB1 / 4 + tid] = gb1[tid];
    if (tid < NE)   smf[OFF_GB2 / 4 + tid] = gb2[tid];
    const float b2v = eb2[wid];

    // ---- expert W1 B-fragments in registers (fp16, single rounding) ----
    uint32_t bh[8][4][2];
    {
        const float* we = ew1 + wid * DIM * NH;
        const int n  = (lane >> 2);
        const int kb = (lane & 3) * 2;
        #pragma unroll
        for (int nf = 0; nf < 8; nf++) {
            #pragma unroll
            for (int kk = 0; kk < 4; kk++) {
                const int k0 = kk * 16 + kb;
                bh[nf][kk][0] = packh2(we[(k0 + 0) * NH + nf * 8 + n],
                                       we[(k0 + 1) * NH + nf * 8 + n]);
                bh[nf][kk][1] = packh2(we[(k0 + 8) * NH + nf * 8 + n],
                                       we[(k0 + 9) * NH + nf * 8 + n]);
            }
        }
    }

    const int rl = (lane & 7) + ((lane >> 3) & 1) * 8;
    const uint32_t pb  = (uint32_t)(rl * 128 + ((lane >> 4) * 16));
    const uint32_t swt = ((uint32_t)(rl * 128) >> 3) & 0x70;
    const int crow = tid >> 4;          // this thread's chunk rows: crow + w*16
    const int cc4  = tid & 15;          // fixed 16B column chunk
    const int grow = tid >> 1;          // gating: pair -> row
    const int ghalf = tid & 1;          // which 16 hidden units
    const int jb = ghalf * 16;

    // ---- prologue: prefetch first tile into RAW (each thread its own chunks) ----
    {
        const int rowBase = blockIdx.x * TILE_M;
        #pragma unroll
        for (int w = 0; w < 8; w++) {
            int row = crow + w * 16;
            const float4* src = (cc4 < 8)
                ? (const float4*)(A + (rowBase + row) * 32) + cc4
                : (const float4*)(S + (rowBase + row) * 32) + (cc4 - 8);
            cpasync16(sbase + OFF_RAW + row * 256 + cc4 * 16, src);
        }
        CP_COMMIT;
    }
    __syncthreads();

    for (int tile = blockIdx.x; tile < NTILES; tile += GRID) {
        const int rowBase = tile * TILE_M;
        CP_WAIT0;   // my prefetched chunks are in RAW

        // ---- convert: RAW (LDS) -> fp16 SW128 XHI (+ transposed fp32 S) ----
        #pragma unroll
        for (int w = 0; w < 8; w++) {
            int row = crow + w * 16;
            float4 v = *(const float4*)(smem + OFF_RAW + row * 256 + cc4 * 16);
            uint2 hp;
            hp.x = cvth2(v.x, v.y);
            hp.y = cvth2(v.z, v.w);
            *(uint2*)(smem + OFF_XHI + SW((uint32_t)(row * 128 + cc4 * 8))) = hp;
            if (cc4 >= 8) {
                int k = (cc4 - 8) * 4;
                smf[OFF_ST / 4 + (k + 0) * 129 + row] = v.x;
                smf[OFF_ST / 4 + (k + 1) * 129 + row] = v.y;
                smf[OFF_ST / 4 + (k + 2) * 129 + row] = v.z;
                smf[OFF_ST / 4 + (k + 3) * 129 + row] = v.w;
            }
        }
        // ---- prefetch next tile into RAW (own chunks; overlaps gating+GEMM) ----
        {
            int nt = tile + GRID;
            if (nt < NTILES) {
                const int rb = nt * TILE_M;
                #pragma unroll
                for (int w = 0; w < 8; w++) {
                    int row = crow + w * 16;
                    const float4* src = (cc4 < 8)
                        ? (const float4*)(A + (rb + row) * 32) + cc4
                        : (const float4*)(S + (rb + row) * 32) + (cc4 - 8);
                    cpasync16(sbase + OFF_RAW + row * 256 + cc4 * 16, src);
                }
            }
            CP_COMMIT;
        }
        __syncthreads();   // barrier 1: XHI + ST ready

        // ---- gating MLP: ALL warps, 2 threads per row (16 hidden units each),
        //      partial logits combined in-warp via shfl ----
        {
            ull h2[8];
            #pragma unroll
            for (int p = 0; p < 8; p++)
                h2[p] = *(const ull*)(smf + OFF_GB1 / 4 + jb + 2 * p);
            #pragma unroll 4
            for (int k = 0; k < GHID; k++) {
                float sv = smf[OFF_ST / 4 + k * 129 + grow];
                ull s2 = pack2(sv, sv);
                const ulonglong2* wr =
                    (const ulonglong2*)(smem + OFF_GW1 + k * 128 + jb * 4);
                #pragma unroll
                for (int j = 0; j < 4; j++) {
                    ulonglong2 w = wr[j];
                    h2[2 * j]     = fma2(s2, w.x, h2[2 * j]);
                    h2[2 * j + 1] = fma2(s2, w.y, h2[2 * j + 1]);
                }
            }
            ull l2[4];
            #pragma unroll
            for (int e2 = 0; e2 < 4; e2++)
                l2[e2] = ghalf ? 0ull
                       : *(const ull*)(smf + OFF_GB2 / 4 + 2 * e2);
            #pragma unroll
            for (int p = 0; p < 8; p++) {
                float a, b; unpack2(h2[p], a, b);
                a = fmaxf(a, 0.f); b = fmaxf(b, 0.f);
                ull pa = pack2(a, a), pb2 = pack2(b, b);
                const ulonglong2* wa =
                    (const ulonglong2*)(smem + OFF_GW2 + (jb + 2 * p) * 32);
                const ulonglong2* wb =
                    (const ulonglong2*)(smem + OFF_GW2 + (jb + 2 * p + 1) * 32);
                l2[0] = fma2(pa, wa[0].x, l2[0]); l2[1] = fma2(pa, wa[0].y, l2[1]);
                l2[2] = fma2(pa, wa[1].x, l2[2]); l2[3] = fma2(pa, wa[1].y, l2[3]);
                l2[0] = fma2(pb2, wb[0].x, l2[0]); l2[1] = fma2(pb2, wb[0].y, l2[1]);
                l2[2] = fma2(pb2, wb[1].x, l2[2]); l2[3] = fma2(pb2, wb[1].y, l2[3]);
            }
            float logit[NE];
            #pragma unroll
            for (int e2 = 0; e2 < 4; e2++) unpack2(l2[e2], logit[2 * e2], logit[2 * e2 + 1]);
            #pragma unroll
            for (int e = 0; e < NE; e++)
                logit[e] += __shfl_xor_sync(0xFFFFFFFFu, logit[e], 1);
            if (ghalf == 0) {
                float mx = logit[0];
                #pragma unroll
                for (int e = 1; e < NE; e++) mx = fmaxf(mx, logit[e]);
                float se = 0.f, pr[NE];
                #pragma unroll
                for (int e = 0; e < NE; e++) { pr[e] = __expf(logit[e] - mx); se += pr[e]; }
                float inv = __fdividef(1.f, se);
                #pragma unroll
                for (int e = 0; e < NE; e++)
                    smf[OFF_PROB / 4 + grow * 9 + e] = pr[e] * inv;
            }
        }

        // ---- expert GEMM: single fp16 product, warp = expert ----
        const float* b1w = smf + OFF_B1S / 4 + wid * NH + (lane & 3) * 2;
        const float* w2w = smf + OFF_W2S / 4 + wid * NH + (lane & 3) * 2;
        #pragma unroll 1
        for (int sub = 0; sub < NSUB; sub++) {
            float c[8][4];
            #pragma unroll
            for (int nf = 0; nf < 8; nf++) {
                float b0 = b1w[nf * 8], b1_ = b1w[nf * 8 + 1];
                c[nf][0] = b0; c[nf][1] = b1_; c[nf][2] = b0; c[nf][3] = b1_;
            }
            #pragma unroll
            for (int kk = 0; kk < 4; kk++) {
                uint32_t ah[4];
                uint32_t off = (uint32_t)(sub * 2048) + ((pb + kk * 32) ^ swt);
                ldsm4(ah, sbase + OFF_XHI + off);
                #pragma unroll
                for (int nf = 0; nf < 8; nf++) mma16816(c[nf], ah, bh[nf][kk][0], bh[nf][kk][1]);
            }
            float p0 = 0.f, p1 = 0.f;
            #pragma unroll
            for (int nf = 0; nf < 8; nf++) {
                float w0 = w2w[nf * 8], w1 = w2w[nf * 8 + 1];
                p0 = fmaf(fmaxf(c[nf][0], 0.f), w0, p0);
                p0 = fmaf(fmaxf(c[nf][1], 0.f), w1, p0);
                p1 = fmaf(fmaxf(c[nf][2], 0.f), w0, p1);
                p1 = fmaf(fmaxf(c[nf][3], 0.f), w1, p1);
            }
            p0 += __shfl_xor_sync(0xFFFFFFFFu, p0, 1);
            p0 += __shfl_xor_sync(0xFFFFFFFFu, p0, 2);
            p1 += __shfl_xor_sync(0xFFFFFFFFu, p1, 1);
            p1 += __shfl_xor_sync(0xFFFFFFFFu, p1, 2);
            if ((lane & 3) == 0) {
                int r = sub * 16 + (lane >> 2);
                smf[OFF_EO / 4 + r * 9 + wid]       = p0 + b2v;
                smf[OFF_EO / 4 + (r + 8) * 9 + wid] = p1 + b2v;
            }
        }
        __syncthreads();   // barrier 2: EO + PROB ready (and XHI/ST consumed)

        // ---- final: weighted sum over experts ----
        if (tid < TILE_M) {
            const float* pr = smf + OFF_PROB / 4 + tid * 9;
            const float* eo = smf + OFF_EO / 4 + tid * 9;
            float r = 0.f;
            #pragma unroll
            for (int e = 0; e < NE; e++) r = fmaf(pr[e], eo[e], r);
            out[rowBase + tid] = r;
        }
    }
}

extern "C" void kernel_launch(void* const* d_in, const int* in_sizes, int n_in,
                              void* d_out, int out_size)
{
    (void)in_sizes; (void)n_in; (void)out_size;
    const float* A   = (const float*)d_in[0];
    const float* S   = (const float*)d_in[1];
    const float* gw1 = (const float*)d_in[2];
    const float* gb1 = (const float*)d_in[3];
    const float* gw2 = (const float*)d_in[4];
    const float* gb2 = (const float*)d_in[5];
    const float* ew1 = (const float*)d_in[6];
    const float* eb1 = (const float*)d_in[7];
    const float* ew2 = (const float*)d_in[8];
    const float* eb2 = (const float*)d_in[9];
    float* out = (float*)d_out;

    cudaFuncSetAttribute(moe_mma_kernel, cudaFuncAttributeMaxDynamicSharedMemorySize, SMEM_BYTES);
    moe_mma_kernel<<<GRID, THREADS, SMEM_BYTES>>>(
        A, S, gw1, gb1, gw2, gb2, ew1, eb1, ew2, eb2, out);
}

// round 17
// speedup vs baseline: 1.0884x; 1.0884x over previous
#include <cuda_runtime.h>
#include <cuda_fp16.h>
#include <cstdint>

#define BATCH   524288
#define DIM     64
#define NE      8
#define NH      64
#define GHID    32

#define TILE_M  128
#define NTILES  (BATCH / TILE_M)   // 4096
#define GRID    296                // 2 CTAs per SM
#define THREADS 256
#define NSUB    8

// ---------------- smem byte layout ----------------
#define OFF_RAW    0        // raw fp32 x [128][64] staged via cp.async = 32768
#define OFF_XHI    32768    // fp16 [128][64] SW128 = 16384
#define OFF_ST     49152    // fp32 S transposed [32][129] = 16512
#define OFF_GW1    65664    // fp32 [32][32] = 4096
#define OFF_GW2    69760    // fp32 [32][8] = 1024
#define OFF_GB1    70784    // fp32 [32] = 128
#define OFF_GB2    70912    // fp32 [8] = 32
#define OFF_PROB   70944    // fp32 [128][9] = 4608 (pitch 9, conflict-free)
#define OFF_EO     75552    // fp32 [128][9] = 4608
#define OFF_W2S    80160    // fp32 [8][64] = 2048
#define OFF_B1S    82208    // fp32 [8][64] = 2048
#define SMEM_BYTES 84256

#define SW(o) ((o) ^ (((o) >> 3) & 0x70))

static __device__ __forceinline__ uint32_t smem_u32(const void* p) {
    uint32_t a;
    asm("{ .reg .u64 t; cvta.to.shared.u64 t, %1; cvt.u32.u64 %0, t; }" : "=r"(a) : "l"(p));
    return a;
}
static __device__ __forceinline__ void cpasync16(uint32_t dst, const void* src) {
    size_t g = __cvta_generic_to_global(src);
    asm volatile("cp.async.cg.shared.global [%0], [%1], 16;" :: "r"(dst), "l"(g) : "memory");
}
#define CP_COMMIT asm volatile("cp.async.commit_group;" ::: "memory")
#define CP_WAIT0  asm volatile("cp.async.wait_group 0;" ::: "memory")

static __device__ __forceinline__ void ldsm4(uint32_t* r, uint32_t addr) {
    asm volatile("ldmatrix.sync.aligned.m8n8.x4.shared.b16 {%0,%1,%2,%3}, [%4];"
                 : "=r"(r[0]), "=r"(r[1]), "=r"(r[2]), "=r"(r[3]) : "r"(addr));
}
static __device__ __forceinline__ void mma16816(float* c, const uint32_t* a,
                                                uint32_t b0, uint32_t b1) {
    asm volatile(
        "mma.sync.aligned.m16n8k16.row.col.f32.f16.f16.f32 "
        "{%0,%1,%2,%3}, {%4,%5,%6,%7}, {%8,%9}, {%0,%1,%2,%3};"
        : "+f"(c[0]), "+f"(c[1]), "+f"(c[2]), "+f"(c[3])
        : "r"(a[0]), "r"(a[1]), "r"(a[2]), "r"(a[3]), "r"(b0), "r"(b1));
}

typedef unsigned long long ull;
static __device__ __forceinline__ ull fma2(ull a, ull b, ull c) {
    ull d;
    asm("fma.rn.f32x2 %0, %1, %2, %3;" : "=l"(d) : "l"(a), "l"(b), "l"(c));
    return d;
}
static __device__ __forceinline__ ull pack2(float x, float y) {
    ull d;
    asm("mov.b64 %0, {%1, %2};" : "=l"(d) : "f"(x), "f"(y));
    return d;
}
static __device__ __forceinline__ void unpack2(ull v, float& x, float& y) {
    asm("mov.b64 {%0, %1}, %2;" : "=f"(x), "=f"(y) : "l"(v));
}
static __device__ __forceinline__ uint32_t packh2(float a, float b) {
    __half ha = __float2half_rn(a), hb = __float2half_rn(b);
    return ((uint32_t)__half_as_ushort(hb) << 16) | __half_as_ushort(ha);
}
static __device__ __forceinline__ uint32_t cvth2(float a, float b) {
    uint32_t r;
    asm("cvt.rn.f16x2.f32 %0, %1, %2;" : "=r"(r) : "f"(b), "f"(a));
    return r;
}

__global__ void __launch_bounds__(THREADS, 2)
moe_mma_kernel(const float* __restrict__ A,   const float* __restrict__ S,
               const float* __restrict__ gw1, const float* __restrict__ gb1,
               const float* __restrict__ gw2, const float* __restrict__ gb2,
               const float* __restrict__ ew1, const float* __restrict__ eb1,
               const float* __restrict__ ew2, const float* __restrict__ eb2,
               float* __restrict__ out)
{
    extern __shared__ char smem[];
    float* smf = (float*)smem;
    const uint32_t sbase = smem_u32(smem);
    const int tid  = threadIdx.x;
    const int lane = tid & 31;
    const int wid  = tid >> 5;          // warp == expert id

    // ---- stage small fp32 weights ----
    for (int i = tid; i < GHID * GHID; i += THREADS) smf[OFF_GW1 / 4 + i] = gw1[i];
    for (int i = tid; i < GHID * NE;   i += THREADS) smf[OFF_GW2 / 4 + i] = gw2[i];
    for (int i = tid; i < NE * NH;     i += THREADS) {
        smf[OFF_W2S / 4 + i] = ew2[i];
        smf[OFF_B1S / 4 + i] = eb1[i];
    }
    if (tid < GHID) smf[OFF_GB1 / 4 + tid] = gb1[tid];
    if (tid < NE)   smf[OFF_GB2 / 4 + tid] = gb2[tid];
    const float b2v = eb2[wid];

    // ---- expert W1 B-fragments in registers (fp16, single rounding) ----
    uint32_t bh[8][4][2];
    {
        const float* we = ew1 + wid * DIM * NH;
        const int n  = (lane >> 2);
        const int kb = (lane & 3) * 2;
        #pragma unroll
        for (int nf = 0; nf < 8; nf++) {
            #pragma unroll
            for (int kk = 0; kk < 4; kk++) {
                const int k0 = kk * 16 + kb;
                bh[nf][kk][0] = packh2(we[(k0 + 0) * NH + nf * 8 + n],
                                       we[(k0 + 1) * NH + nf * 8 + n]);
                bh[nf][kk][1] = packh2(we[(k0 + 8) * NH + nf * 8 + n],
                                       we[(k0 + 9) * NH + nf * 8 + n]);
            }
        }
    }

    const int rl = (lane & 7) + ((lane >> 3) & 1) * 8;
    const uint32_t pb  = (uint32_t)(rl * 128 + ((lane >> 4) * 16));
    const uint32_t swt = ((uint32_t)(rl * 128) >> 3) & 0x70;
    const int crow = tid >> 4;          // this thread's chunk rows: crow + w*16
    const int cc4  = tid & 15;          // fixed 16B column chunk

    // ---- prologue: prefetch first tile into RAW (each thread its own chunks) ----
    {
        const int rowBase = blockIdx.x * TILE_M;
        #pragma unroll
        for (int w = 0; w < 8; w++) {
            int row = crow + w * 16;
            const float4* src = (cc4 < 8)
                ? (const float4*)(A + (rowBase + row) * 32) + cc4
                : (const float4*)(S + (rowBase + row) * 32) + (cc4 - 8);
            cpasync16(sbase + OFF_RAW + row * 256 + cc4 * 16, src);
        }
        CP_COMMIT;
    }
    __syncthreads();

    for (int tile = blockIdx.x; tile < NTILES; tile += GRID) {
        const int rowBase = tile * TILE_M;
        CP_WAIT0;   // my prefetched chunks are in RAW

        // ---- convert: RAW (LDS) -> fp16 SW128 XHI (+ transposed fp32 S) ----
        #pragma unroll
        for (int w = 0; w < 8; w++) {
            int row = crow + w * 16;
            float4 v = *(const float4*)(smem + OFF_RAW + row * 256 + cc4 * 16);
            uint2 hp;
            hp.x = cvth2(v.x, v.y);
            hp.y = cvth2(v.z, v.w);
            *(uint2*)(smem + OFF_XHI + SW((uint32_t)(row * 128 + cc4 * 8))) = hp;
            if (cc4 >= 8) {
                int k = (cc4 - 8) * 4;
                smf[OFF_ST / 4 + (k + 0) * 129 + row] = v.x;
                smf[OFF_ST / 4 + (k + 1) * 129 + row] = v.y;
                smf[OFF_ST / 4 + (k + 2) * 129 + row] = v.z;
                smf[OFF_ST / 4 + (k + 3) * 129 + row] = v.w;
            }
        }
        // ---- prefetch next tile into RAW (own chunks; overlaps gating+GEMM) ----
        {
            int nt = tile + GRID;
            if (nt < NTILES) {
                const int rb = nt * TILE_M;
                #pragma unroll
                for (int w = 0; w < 8; w++) {
                    int row = crow + w * 16;
                    const float4* src = (cc4 < 8)
                        ? (const float4*)(A + (rb + row) * 32) + cc4
                        : (const float4*)(S + (rb + row) * 32) + (cc4 - 8);
                    cpasync16(sbase + OFF_RAW + row * 256 + cc4 * 16, src);
                }
            }
            CP_COMMIT;
        }
        __syncthreads();   // barrier 1: XHI + ST ready

        // ---- gating MLP: warps 0-3, one full row per thread (from ST, fp32) ----
        if (tid < TILE_M) {
            ull h2[16];
            #pragma unroll
            for (int p = 0; p < 16; p++)
                h2[p] = *(const ull*)(smf + OFF_GB1 / 4 + 2 * p);
            #pragma unroll 4
            for (int k = 0; k < GHID; k++) {
                float sv = smf[OFF_ST / 4 + k * 129 + tid];
                ull s2 = pack2(sv, sv);
                const ulonglong2* wr = (const ulonglong2*)(smem + OFF_GW1 + k * 128);
                #pragma unroll
                for (int j = 0; j < 8; j++) {
                    ulonglong2 w = wr[j];
                    h2[2 * j]     = fma2(s2, w.x, h2[2 * j]);
                    h2[2 * j + 1] = fma2(s2, w.y, h2[2 * j + 1]);
                }
            }
            ull l2[4];
            {
                ulonglong2 b = *(const ulonglong2*)(smem + OFF_GB2);
                l2[0] = b.x; l2[1] = b.y;
                b = *(const ulonglong2*)(smem + OFF_GB2 + 16);
                l2[2] = b.x; l2[3] = b.y;
            }
            #pragma unroll
            for (int p = 0; p < 16; p++) {
                float a, b; unpack2(h2[p], a, b);
                a = fmaxf(a, 0.f); b = fmaxf(b, 0.f);
                ull pa = pack2(a, a), pb2 = pack2(b, b);
                ulonglong2 wa0 = *(const ulonglong2*)(smem + OFF_GW2 + (2 * p) * 32);
                ulonglong2 wa1 = *(const ulonglong2*)(smem + OFF_GW2 + (2 * p) * 32 + 16);
                ulonglong2 wb0 = *(const ulonglong2*)(smem + OFF_GW2 + (2 * p + 1) * 32);
                ulonglong2 wb1 = *(const ulonglong2*)(smem + OFF_GW2 + (2 * p + 1) * 32 + 16);
                l2[0] = fma2(pa, wa0.x, l2[0]); l2[1] = fma2(pa, wa0.y, l2[1]);
                l2[2] = fma2(pa, wa1.x, l2[2]); l2[3] = fma2(pa, wa1.y, l2[3]);
                l2[0] = fma2(pb2, wb0.x, l2[0]); l2[1] = fma2(pb2, wb0.y, l2[1]);
                l2[2] = fma2(pb2, wb1.x, l2[2]); l2[3] = fma2(pb2, wb1.y, l2[3]);
            }
            float logit[NE];
            #pragma unroll
            for (int e2 = 0; e2 < 4; e2++) unpack2(l2[e2], logit[2 * e2], logit[2 * e2 + 1]);
            float mx = logit[0];
            #pragma unroll
            for (int e = 1; e < NE; e++) mx = fmaxf(mx, logit[e]);
            float se = 0.f, pr[NE];
            #pragma unroll
            for (int e = 0; e < NE; e++) { pr[e] = __expf(logit[e] - mx); se += pr[e]; }
            float inv = __fdividef(1.f, se);
            #pragma unroll
            for (int e = 0; e < NE; e++) smf[OFF_PROB / 4 + tid * 9 + e] = pr[e] * inv;
        }

        // ---- expert GEMM: single fp16 product, warp = expert ----
        const float* b1w = smf + OFF_B1S / 4 + wid * NH + (lane & 3) * 2;
        const float* w2w = smf + OFF_W2S / 4 + wid * NH + (lane & 3) * 2;
        #pragma unroll 1
        for (int sub = 0; sub < NSUB; sub++) {
            float c[8][4];
            #pragma unroll
            for (int nf = 0; nf < 8; nf++) {
                float b0 = b1w[nf * 8], b1_ = b1w[nf * 8 + 1];
                c[nf][0] = b0; c[nf][1] = b1_; c[nf][2] = b0; c[nf][3] = b1_;
            }
            #pragma unroll
            for (int kk = 0; kk < 4; kk++) {
                uint32_t ah[4];
                uint32_t off = (uint32_t)(sub * 2048) + ((pb + kk * 32) ^ swt);
                ldsm4(ah, sbase + OFF_XHI + off);
                #pragma unroll
                for (int nf = 0; nf < 8; nf++) mma16816(c[nf], ah, bh[nf][kk][0], bh[nf][kk][1]);
            }
            float p0 = 0.f, p1 = 0.f;
            #pragma unroll
            for (int nf = 0; nf < 8; nf++) {
                float w0 = w2w[nf * 8], w1 = w2w[nf * 8 + 1];
                p0 = fmaf(fmaxf(c[nf][0], 0.f), w0, p0);
                p0 = fmaf(fmaxf(c[nf][1], 0.f), w1, p0);
                p1 = fmaf(fmaxf(c[nf][2], 0.f), w0, p1);
                p1 = fmaf(fmaxf(c[nf][3], 0.f), w1, p1);
            }
            p0 += __shfl_xor_sync(0xFFFFFFFFu, p0, 1);
            p0 += __shfl_xor_sync(0xFFFFFFFFu, p0, 2);
            p1 += __shfl_xor_sync(0xFFFFFFFFu, p1, 1);
            p1 += __shfl_xor_sync(0xFFFFFFFFu, p1, 2);
            if ((lane & 3) == 0) {
                int r = sub * 16 + (lane >> 2);
                smf[OFF_EO / 4 + r * 9 + wid]       = p0 + b2v;
                smf[OFF_EO / 4 + (r + 8) * 9 + wid] = p1 + b2v;
            }
        }
        __syncthreads();   // barrier 2: EO + PROB ready (and XHI/ST consumed)

        // ---- final: weighted sum over experts ----
        if (tid < TILE_M) {
            const float* pr = smf + OFF_PROB / 4 + tid * 9;
            const float* eo = smf + OFF_EO / 4 + tid * 9;
            float r = 0.f;
            #pragma unroll
            for (int e = 0; e < NE; e++) r = fmaf(pr[e], eo[e], r);
            out[rowBase + tid] = r;
        }
    }
}

extern "C" void kernel_launch(void* const* d_in, const int* in_sizes, int n_in,
                              void* d_out, int out_size)
{
    (void)in_sizes; (void)n_in; (void)out_size;
    const float* A   = (const float*)d_in[0];
    const float* S   = (const float*)d_in[1];
    const float* gw1 = (const float*)d_in[2];
    const float* gb1 = (const float*)d_in[3];
    const float* gw2 = (const float*)d_in[4];
    const float* gb2 = (const float*)d_in[5];
    const float* ew1 = (const float*)d_in[6];
    const float* eb1 = (const float*)d_in[7];
    const float* ew2 = (const float*)d_in[8];
    const float* eb2 = (const float*)d_in[9];
    float* out = (float*)d_out;

    cudaFuncSetAttribute(moe_mma_kernel, cudaFuncAttributeMaxDynamicSharedMemorySize, SMEM_BYTES);
    moe_mma_kernel<<<GRID, THREADS, SMEM_BYTES>>>(
        A, S, gw1, gb1, gw2, gb2, ew1, eb1, ew2, eb2, out);
}